// round 6
// baseline (speedup 1.0000x reference)
#include <cuda_runtime.h>
#include <cuda_bf16.h>
#include <cstdint>

// GraphSAGE 2-layer.
//   p1 = x @ W_l1^T, q1 = x @ W_r1^T     (GEMM1 tf32 tensor-core, dense 64-wide outputs)
//   s1    = scatter-add p1[src] at dst ; deg = scatter-add 1
//   h     = relu(s1/max(deg,1) + b1 + q1)
//   s2    = scatter-add h[src] at dst
//   out   = [s2*rdeg | h] @ [W_l2 | W_r2]^T + b2   (GEMM2 tf32 tensor-core)
//
// NOTE: __device__ globals are referenced ONLY inside kernels.

#define NMAX 100000

__device__ __align__(16) float g_p1  [(size_t)NMAX * 64];
__device__ __align__(16) float g_q1  [(size_t)NMAX * 64];
__device__ __align__(16) float g_s1  [(size_t)NMAX * 64];
__device__ __align__(16) float g_h   [(size_t)NMAX * 64];
__device__ __align__(16) float g_s2  [(size_t)NMAX * 64];
__device__ __align__(16) float g_deg [NMAX];
__device__ __align__(16) float g_rdeg[NMAX];

// ---------------------------------------------------------------------------
// zero accumulators
// ---------------------------------------------------------------------------
__global__ void zero_kernel(int N) {
    int gid = blockIdx.x * 256 + threadIdx.x;           // N*16 threads
    float4 z = make_float4(0.f, 0.f, 0.f, 0.f);
    int n16 = N * 16;
    if (gid < n16) {
        reinterpret_cast<float4*>(g_s1)[gid] = z;
        reinterpret_cast<float4*>(g_s2)[gid] = z;
    }
    if (gid < (N + 3) / 4) {
        reinterpret_cast<float4*>(g_deg)[gid] = z;
    }
}

// ---------------------------------------------------------------------------
// tf32 tensor-core GEMM
// Block: 256 threads (8 warps, 4x2), tile 128(M) x 128(N), K chunked by 32.
// Warp tile 32x64 via m16n8k8: 2 m-tiles x 8 n-tiles, 4 k-steps per chunk.
// smem paired-k layout: koff(kl) -> (k, k+4) adjacent, frag = one LDS.64.
// LDC = 40 floats; static smem 40 KB < 48 KB default.
// ---------------------------------------------------------------------------
#define LDC 40

__device__ __forceinline__ uint32_t f2tf32(float f) {
    uint32_t o; asm("cvt.rna.tf32.f32 %0, %1;" : "=r"(o) : "f"(f)); return o;
}
__device__ __forceinline__ int koff(int kl) {
    return (kl & ~7) + ((kl & 3) << 1) + ((kl >> 2) & 1);
}

#define MMA4(c, a, b) asm volatile( \
  "mma.sync.aligned.m16n8k8.row.col.f32.tf32.tf32.f32 " \
  "{%0,%1,%2,%3},{%4,%5,%6,%7},{%8,%9},{%0,%1,%2,%3};" \
  : "+f"(c[0]), "+f"(c[1]), "+f"(c[2]), "+f"(c[3]) \
  : "r"(a[0]), "r"(a[1]), "r"(a[2]), "r"(a[3]), "r"(b.x), "r"(b.y))

// MODE 1: A = x [N,128]; B rows: n<64 -> Wl1[n,:], else Wr1[n-64,:];
//         writes cols 0..63 -> g_p1 (dense 64), cols 64..127 -> g_q1 (dense 64)
// MODE 2: A cols 0..63 = s2*rdeg, 64..127 = h; B: k<64 -> Wl2, else Wr2; +bias; writes outp
template<int MODE>
__global__ __launch_bounds__(256, 2) void gemm_tc(
    const float* __restrict__ x,
    const float* __restrict__ Wl, const float* __restrict__ Wr,
    const float* __restrict__ bias, float* __restrict__ outp, int N)
{
    __shared__ uint32_t As[128 * LDC];
    __shared__ uint32_t Bs[128 * LDC];
    const int tid  = threadIdx.x;
    const int m0   = blockIdx.x * 128;
    const int lane = tid & 31, warp = tid >> 5;
    const int g    = lane >> 2, t = lane & 3;
    const int rm   = (warp >> 1) * 32;
    const int cn   = (warp & 1) * 64;

    float acc[2][8][4];
#pragma unroll
    for (int i = 0; i < 2; i++)
#pragma unroll
        for (int j = 0; j < 8; j++)
#pragma unroll
            for (int q = 0; q < 4; q++) acc[i][j][q] = 0.f;

#pragma unroll
    for (int kc = 0; kc < 128; kc += 32) {
        if (kc) __syncthreads();
        // ---- stage A chunk (128 rows x 32 k) ----
#pragma unroll
        for (int it = 0; it < 4; it++) {
            int f = tid + it * 256;          // 0..1023
            int row = f >> 3, q = f & 7;     // row 0..127, q = float4 index 0..7
            int gm = m0 + row;
            float4 v = make_float4(0.f, 0.f, 0.f, 0.f);
            if (MODE == 1) {
                if (gm < N)
                    v = *reinterpret_cast<const float4*>(x + (size_t)gm * 128 + kc + q * 4);
            } else {
                if (gm < N) {
                    if (kc < 64) {
                        v = *reinterpret_cast<const float4*>(g_s2 + (size_t)gm * 64 + kc + q * 4);
                        float r = g_rdeg[gm];
                        v.x *= r; v.y *= r; v.z *= r; v.w *= r;
                    } else {
                        v = *reinterpret_cast<const float4*>(g_h + (size_t)gm * 64 + (kc - 64) + q * 4);
                    }
                }
            }
            int kl = q * 4;
            uint32_t* dst = As + row * LDC;
            dst[koff(kl + 0)] = f2tf32(v.x);
            dst[koff(kl + 1)] = f2tf32(v.y);
            dst[koff(kl + 2)] = f2tf32(v.z);
            dst[koff(kl + 3)] = f2tf32(v.w);
        }
        // ---- stage B chunk (128 n x 32 k) ----
#pragma unroll
        for (int it = 0; it < 4; it++) {
            int f = tid + it * 256;
            int n = f >> 3, q = f & 7;
            const float* src;
            if (MODE == 1)
                src = (n < 64) ? (Wl + (size_t)n * 128 + kc + q * 4)
                               : (Wr + (size_t)(n - 64) * 128 + kc + q * 4);
            else
                src = ((kc < 64) ? (Wl + (size_t)n * 64 + kc)
                                 : (Wr + (size_t)n * 64 + (kc - 64))) + q * 4;
            float4 v = *reinterpret_cast<const float4*>(src);
            int kl = q * 4;
            uint32_t* dst = Bs + n * LDC;
            dst[koff(kl + 0)] = f2tf32(v.x);
            dst[koff(kl + 1)] = f2tf32(v.y);
            dst[koff(kl + 2)] = f2tf32(v.z);
            dst[koff(kl + 3)] = f2tf32(v.w);
        }
        __syncthreads();
        // ---- compute: 4 k-steps of m16n8k8 ----
#pragma unroll
        for (int s = 0; s < 4; s++) {
            uint32_t a[2][4];
#pragma unroll
            for (int mt = 0; mt < 2; mt++) {
                int m = rm + mt * 16 + g;
                uint2 lo = *reinterpret_cast<const uint2*>(As + m * LDC + s * 8 + t * 2);
                uint2 hi = *reinterpret_cast<const uint2*>(As + (m + 8) * LDC + s * 8 + t * 2);
                a[mt][0] = lo.x; a[mt][1] = hi.x; a[mt][2] = lo.y; a[mt][3] = hi.y;
            }
#pragma unroll
            for (int nt = 0; nt < 8; nt++) {
                uint2 b = *reinterpret_cast<const uint2*>(Bs + (cn + nt * 8 + g) * LDC + s * 8 + t * 2);
                MMA4(acc[0][nt], a[0], b);
                MMA4(acc[1][nt], a[1], b);
            }
        }
    }
    // ---- epilogue ----
#pragma unroll
    for (int mt = 0; mt < 2; mt++) {
#pragma unroll
        for (int nt = 0; nt < 8; nt++) {
            int row = m0 + rm + mt * 16 + g;
            int col = cn + nt * 8 + t * 2;
            if (MODE == 1) {
                // cols 0..63 -> g_p1, 64..127 -> g_q1 (both dense, stride 64)
                float* buf = (cn == 0) ? g_p1 : g_q1;
                int c64 = nt * 8 + t * 2;
                if (row < N)
                    *reinterpret_cast<float2*>(buf + (size_t)row * 64 + c64) =
                        make_float2(acc[mt][nt][0], acc[mt][nt][1]);
                if (row + 8 < N)
                    *reinterpret_cast<float2*>(buf + (size_t)(row + 8) * 64 + c64) =
                        make_float2(acc[mt][nt][2], acc[mt][nt][3]);
            } else {
                float2 bb = *reinterpret_cast<const float2*>(bias + col);
                if (row < N)
                    *reinterpret_cast<float2*>(outp + (size_t)row * 128 + col) =
                        make_float2(acc[mt][nt][0] + bb.x, acc[mt][nt][1] + bb.y);
                if (row + 8 < N)
                    *reinterpret_cast<float2*>(outp + (size_t)(row + 8) * 128 + col) =
                        make_float2(acc[mt][nt][2] + bb.x, acc[mt][nt][3] + bb.y);
            }
        }
    }
}

// ---------------------------------------------------------------------------
// scatter: 8 threads per edge, each lane moves 32B via 2x red.global.add.v4.f32
// LAYER 1: feat = g_p1 (dense 64), out = g_s1, also count deg
// LAYER 2: feat = g_h  (dense 64), out = g_s2
// ---------------------------------------------------------------------------
template <int LAYER>
__global__ void scatter_kernel(const int* __restrict__ ei, int E) {
    int gid = blockIdx.x * 256 + threadIdx.x;
    int e = gid >> 3;
    if (e >= E) return;
    int part = gid & 7;
    int s = __ldg(ei + e);
    int d = __ldg(ei + E + e);
    const float* feat = (LAYER == 1) ? g_p1 : g_h;
    const float* src = feat + (size_t)s * 64 + part * 8;
    float4 v0 = *reinterpret_cast<const float4*>(src);
    float4 v1 = *reinterpret_cast<const float4*>(src + 4);
    float* outp = ((LAYER == 1) ? g_s1 : g_s2) + (size_t)d * 64 + part * 8;
    asm volatile("red.global.add.v4.f32 [%0], {%1,%2,%3,%4};"
                 :: "l"(outp), "f"(v0.x), "f"(v0.y), "f"(v0.z), "f"(v0.w) : "memory");
    asm volatile("red.global.add.v4.f32 [%0], {%1,%2,%3,%4};"
                 :: "l"(outp + 4), "f"(v1.x), "f"(v1.y), "f"(v1.z), "f"(v1.w) : "memory");
    if (LAYER == 1 && part == 0)
        atomicAdd(&g_deg[d], 1.0f);
}

// ---------------------------------------------------------------------------
// h = relu(s1/max(deg,1) + b1 + q1) ; also store rdeg = 1/max(deg,1)
// ---------------------------------------------------------------------------
__global__ void h_kernel(const float* __restrict__ b1, int N) {
    int gid = blockIdx.x * 256 + threadIdx.x;   // N*16 threads
    int node = gid >> 4;
    if (node >= N) return;
    int part = gid & 15;
    float r = 1.0f / fmaxf(g_deg[node], 1.0f);
    if (part == 0) g_rdeg[node] = r;
    float4 sv = *reinterpret_cast<const float4*>(g_s1 + (size_t)node * 64 + part * 4);
    float4 qv = *reinterpret_cast<const float4*>(g_q1 + (size_t)node * 64 + part * 4);
    float4 bv = *reinterpret_cast<const float4*>(b1 + part * 4);
    float4 hv;
    hv.x = fmaxf(sv.x * r + bv.x + qv.x, 0.f);
    hv.y = fmaxf(sv.y * r + bv.y + qv.y, 0.f);
    hv.z = fmaxf(sv.z * r + bv.z + qv.z, 0.f);
    hv.w = fmaxf(sv.w * r + bv.w + qv.w, 0.f);
    *reinterpret_cast<float4*>(g_h + (size_t)node * 64 + part * 4) = hv;
}

// ---------------------------------------------------------------------------
extern "C" void kernel_launch(void* const* d_in, const int* in_sizes, int n_in,
                              void* d_out, int out_size)
{
    const float* x   = (const float*)d_in[0];
    const int*   ei  = (const int*)  d_in[1];
    const float* Wl1 = (const float*)d_in[2];
    const float* Wr1 = (const float*)d_in[3];
    const float* b1  = (const float*)d_in[4];
    const float* Wl2 = (const float*)d_in[5];
    const float* Wr2 = (const float*)d_in[6];
    const float* b2  = (const float*)d_in[7];
    float* out = (float*)d_out;

    int N = in_sizes[0] / 128;
    int E = in_sizes[1] / 2;

    int zgrid = (N * 16 + 255) / 256;
    int ggrid = (N + 127) / 128;
    long sthreads = (long)E * 8;
    int sgrid = (int)((sthreads + 255) / 256);

    zero_kernel<<<zgrid, 256>>>(N);
    gemm_tc<1><<<ggrid, 256>>>(x, Wl1, Wr1, nullptr, nullptr, N);
    scatter_kernel<1><<<sgrid, 256>>>(ei, E);
    h_kernel<<<zgrid, 256>>>(b1, N);
    scatter_kernel<2><<<sgrid, 256>>>(ei, E);
    gemm_tc<2><<<ggrid, 256>>>(nullptr, Wl2, Wr2, b2, out, N);
}

// round 7
// speedup vs baseline: 1.6080x; 1.6080x over previous
#include <cuda_runtime.h>
#include <cuda_bf16.h>
#include <cstdint>

// GraphSAGE 2-layer, CSR-pull aggregation (no feature atomics).
//   p1 = x @ W_l1^T, q1 = x @ W_r1^T     (GEMM1 tf32 tensor-core)
//   CSR build: hist(dst) -> scan -> fill   (once per call; degrees for free)
//   s1[n] = sum_{src in csr[n]} p1[src]    (warp-per-node pull)
//   h     = relu(s1/max(deg,1) + b1 + q1)
//   s2[n] = sum_{src in csr[n]} h[src]
//   out   = [s2/deg | h] @ [W_l2 | W_r2]^T + b2   (GEMM2 tf32 tensor-core)
//
// __device__ globals referenced ONLY inside kernels.

#define NMAX 100000
#define EMAX 1600000

__device__ __align__(16) float g_p1    [(size_t)NMAX * 64];
__device__ __align__(16) float g_q1    [(size_t)NMAX * 64];
__device__ __align__(16) float g_s1    [(size_t)NMAX * 64];
__device__ __align__(16) float g_h     [(size_t)NMAX * 64];
__device__ __align__(16) float g_s2    [(size_t)NMAX * 64];
__device__ __align__(16) int   g_cnt   [NMAX];
__device__ __align__(16) int   g_starts[NMAX];
__device__ __align__(16) int   g_cursor[NMAX];
__device__ __align__(16) int   g_bsum  [256];
__device__ __align__(16) int   g_boff  [256];
__device__ __align__(16) int   g_csrc  [EMAX];

// ---------------------------------------------------------------------------
// CSR build
// ---------------------------------------------------------------------------
__global__ void zero_cnt_kernel(int N) {
    int gid = blockIdx.x * 256 + threadIdx.x;
    if (gid * 4 < N) {
        int4 z = make_int4(0, 0, 0, 0);
        reinterpret_cast<int4*>(g_cnt)[gid] = z;
    }
}

__global__ void hist_kernel(const int* __restrict__ ei, int E) {
    int e = blockIdx.x * 256 + threadIdx.x;
    if (e < E) atomicAdd(&g_cnt[__ldg(ei + E + e)], 1);
}

// scan1: 512-wide block inclusive scan of g_cnt -> exclusive to g_starts, block sums
__global__ void scan1_kernel(int N) {
    __shared__ int sm[512];
    int tid = threadIdx.x;
    int gid = blockIdx.x * 512 + tid;
    int v = (gid < N) ? g_cnt[gid] : 0;
    sm[tid] = v;
    __syncthreads();
#pragma unroll
    for (int off = 1; off < 512; off <<= 1) {
        int t = (tid >= off) ? sm[tid - off] : 0;
        __syncthreads();
        sm[tid] += t;
        __syncthreads();
    }
    if (gid < N) g_starts[gid] = sm[tid] - v;          // exclusive within block
    if (tid == 511) g_bsum[blockIdx.x] = sm[511];
}

// scan2: single block scans the (<=256) block sums -> exclusive offsets
__global__ void scan2_kernel(int nb) {
    __shared__ int sm[256];
    int tid = threadIdx.x;
    int v = (tid < nb) ? g_bsum[tid] : 0;
    sm[tid] = v;
    __syncthreads();
#pragma unroll
    for (int off = 1; off < 256; off <<= 1) {
        int t = (tid >= off) ? sm[tid - off] : 0;
        __syncthreads();
        sm[tid] += t;
        __syncthreads();
    }
    if (tid < nb) g_boff[tid] = sm[tid] - v;
}

// scan3: add block offsets; init cursor
__global__ void scan3_kernel(int N) {
    int gid = blockIdx.x * 256 + threadIdx.x;
    if (gid < N) {
        int s = g_starts[gid] + g_boff[gid >> 9];
        g_starts[gid] = s;
        g_cursor[gid] = s;
    }
}

__global__ void fill_kernel(const int* __restrict__ ei, int E) {
    int e = blockIdx.x * 256 + threadIdx.x;
    if (e < E) {
        int s = __ldg(ei + e);
        int d = __ldg(ei + E + e);
        int slot = atomicAdd(&g_cursor[d], 1);
        g_csrc[slot] = s;
    }
}

// ---------------------------------------------------------------------------
// aggregate: one warp per dst node, lanes hold 2 floats each, 2-edge unroll
// LAYER 1: feat = g_p1 -> g_s1 ; LAYER 2: feat = g_h -> g_s2
// ---------------------------------------------------------------------------
template <int LAYER>
__global__ void agg_kernel(int N) {
    int w = (blockIdx.x * 256 + threadIdx.x) >> 5;
    if (w >= N) return;
    int lane = threadIdx.x & 31;
    int beg = g_starts[w];
    int end = beg + g_cnt[w];
    const float* feat = (LAYER == 1) ? g_p1 : g_h;
    float2 acc = make_float2(0.f, 0.f);
    int j = beg;
    for (; j + 2 <= end; j += 2) {
        int s0 = __ldg(g_csrc + j);
        int s1 = __ldg(g_csrc + j + 1);
        float2 a = *reinterpret_cast<const float2*>(feat + (size_t)s0 * 64 + lane * 2);
        float2 b = *reinterpret_cast<const float2*>(feat + (size_t)s1 * 64 + lane * 2);
        acc.x += a.x + b.x;
        acc.y += a.y + b.y;
    }
    if (j < end) {
        int s0 = __ldg(g_csrc + j);
        float2 a = *reinterpret_cast<const float2*>(feat + (size_t)s0 * 64 + lane * 2);
        acc.x += a.x;
        acc.y += a.y;
    }
    float* outb = (LAYER == 1) ? g_s1 : g_s2;
    *reinterpret_cast<float2*>(outb + (size_t)w * 64 + lane * 2) = acc;
}

// ---------------------------------------------------------------------------
// tf32 tensor-core GEMM (unchanged from working round-5/6 version)
// ---------------------------------------------------------------------------
#define LDC 40

__device__ __forceinline__ uint32_t f2tf32(float f) {
    uint32_t o; asm("cvt.rna.tf32.f32 %0, %1;" : "=r"(o) : "f"(f)); return o;
}
__device__ __forceinline__ int koff(int kl) {
    return (kl & ~7) + ((kl & 3) << 1) + ((kl >> 2) & 1);
}

#define MMA4(c, a, b) asm volatile( \
  "mma.sync.aligned.m16n8k8.row.col.f32.tf32.tf32.f32 " \
  "{%0,%1,%2,%3},{%4,%5,%6,%7},{%8,%9},{%0,%1,%2,%3};" \
  : "+f"(c[0]), "+f"(c[1]), "+f"(c[2]), "+f"(c[3]) \
  : "r"(a[0]), "r"(a[1]), "r"(a[2]), "r"(a[3]), "r"(b.x), "r"(b.y))

// MODE 1: A = x [N,128]; B rows: n<64 -> Wl1, else Wr1; writes g_p1 / g_q1
// MODE 2: A cols 0..63 = s2 * (1/max(cnt,1)), 64..127 = h; B: k<64 -> Wl2 else Wr2; +bias
template<int MODE>
__global__ __launch_bounds__(256, 2) void gemm_tc(
    const float* __restrict__ x,
    const float* __restrict__ Wl, const float* __restrict__ Wr,
    const float* __restrict__ bias, float* __restrict__ outp, int N)
{
    __shared__ uint32_t As[128 * LDC];
    __shared__ uint32_t Bs[128 * LDC];
    const int tid  = threadIdx.x;
    const int m0   = blockIdx.x * 128;
    const int lane = tid & 31, warp = tid >> 5;
    const int g    = lane >> 2, t = lane & 3;
    const int rm   = (warp >> 1) * 32;
    const int cn   = (warp & 1) * 64;

    float acc[2][8][4];
#pragma unroll
    for (int i = 0; i < 2; i++)
#pragma unroll
        for (int j = 0; j < 8; j++)
#pragma unroll
            for (int q = 0; q < 4; q++) acc[i][j][q] = 0.f;

#pragma unroll
    for (int kc = 0; kc < 128; kc += 32) {
        if (kc) __syncthreads();
        // ---- stage A chunk ----
#pragma unroll
        for (int it = 0; it < 4; it++) {
            int f = tid + it * 256;
            int row = f >> 3, q = f & 7;
            int gm = m0 + row;
            float4 v = make_float4(0.f, 0.f, 0.f, 0.f);
            if (MODE == 1) {
                if (gm < N)
                    v = *reinterpret_cast<const float4*>(x + (size_t)gm * 128 + kc + q * 4);
            } else {
                if (gm < N) {
                    if (kc < 64) {
                        v = *reinterpret_cast<const float4*>(g_s2 + (size_t)gm * 64 + kc + q * 4);
                        float r = 1.0f / fmaxf((float)g_cnt[gm], 1.0f);
                        v.x *= r; v.y *= r; v.z *= r; v.w *= r;
                    } else {
                        v = *reinterpret_cast<const float4*>(g_h + (size_t)gm * 64 + (kc - 64) + q * 4);
                    }
                }
            }
            int kl = q * 4;
            uint32_t* dst = As + row * LDC;
            dst[koff(kl + 0)] = f2tf32(v.x);
            dst[koff(kl + 1)] = f2tf32(v.y);
            dst[koff(kl + 2)] = f2tf32(v.z);
            dst[koff(kl + 3)] = f2tf32(v.w);
        }
        // ---- stage B chunk ----
#pragma unroll
        for (int it = 0; it < 4; it++) {
            int f = tid + it * 256;
            int n = f >> 3, q = f & 7;
            const float* src;
            if (MODE == 1)
                src = (n < 64) ? (Wl + (size_t)n * 128 + kc + q * 4)
                               : (Wr + (size_t)(n - 64) * 128 + kc + q * 4);
            else
                src = ((kc < 64) ? (Wl + (size_t)n * 64 + kc)
                                 : (Wr + (size_t)n * 64 + (kc - 64))) + q * 4;
            float4 v = *reinterpret_cast<const float4*>(src);
            int kl = q * 4;
            uint32_t* dst = Bs + n * LDC;
            dst[koff(kl + 0)] = f2tf32(v.x);
            dst[koff(kl + 1)] = f2tf32(v.y);
            dst[koff(kl + 2)] = f2tf32(v.z);
            dst[koff(kl + 3)] = f2tf32(v.w);
        }
        __syncthreads();
        // ---- compute ----
#pragma unroll
        for (int s = 0; s < 4; s++) {
            uint32_t a[2][4];
#pragma unroll
            for (int mt = 0; mt < 2; mt++) {
                int m = rm + mt * 16 + g;
                uint2 lo = *reinterpret_cast<const uint2*>(As + m * LDC + s * 8 + t * 2);
                uint2 hi = *reinterpret_cast<const uint2*>(As + (m + 8) * LDC + s * 8 + t * 2);
                a[mt][0] = lo.x; a[mt][1] = hi.x; a[mt][2] = lo.y; a[mt][3] = hi.y;
            }
#pragma unroll
            for (int nt = 0; nt < 8; nt++) {
                uint2 b = *reinterpret_cast<const uint2*>(Bs + (cn + nt * 8 + g) * LDC + s * 8 + t * 2);
                MMA4(acc[0][nt], a[0], b);
                MMA4(acc[1][nt], a[1], b);
            }
        }
    }
    // ---- epilogue ----
#pragma unroll
    for (int mt = 0; mt < 2; mt++) {
#pragma unroll
        for (int nt = 0; nt < 8; nt++) {
            int row = m0 + rm + mt * 16 + g;
            int col = cn + nt * 8 + t * 2;
            if (MODE == 1) {
                float* buf = (cn == 0) ? g_p1 : g_q1;
                int c64 = nt * 8 + t * 2;
                if (row < N)
                    *reinterpret_cast<float2*>(buf + (size_t)row * 64 + c64) =
                        make_float2(acc[mt][nt][0], acc[mt][nt][1]);
                if (row + 8 < N)
                    *reinterpret_cast<float2*>(buf + (size_t)(row + 8) * 64 + c64) =
                        make_float2(acc[mt][nt][2], acc[mt][nt][3]);
            } else {
                float2 bb = *reinterpret_cast<const float2*>(bias + col);
                if (row < N)
                    *reinterpret_cast<float2*>(outp + (size_t)row * 128 + col) =
                        make_float2(acc[mt][nt][0] + bb.x, acc[mt][nt][1] + bb.y);
                if (row + 8 < N)
                    *reinterpret_cast<float2*>(outp + (size_t)(row + 8) * 128 + col) =
                        make_float2(acc[mt][nt][2] + bb.x, acc[mt][nt][3] + bb.y);
            }
        }
    }
}

// ---------------------------------------------------------------------------
// h = relu(s1/max(deg,1) + b1 + q1)
// ---------------------------------------------------------------------------
__global__ void h_kernel(const float* __restrict__ b1, int N) {
    int gid = blockIdx.x * 256 + threadIdx.x;   // N*16 threads
    int node = gid >> 4;
    if (node >= N) return;
    int part = gid & 15;
    float r = 1.0f / fmaxf((float)g_cnt[node], 1.0f);
    float4 sv = *reinterpret_cast<const float4*>(g_s1 + (size_t)node * 64 + part * 4);
    float4 qv = *reinterpret_cast<const float4*>(g_q1 + (size_t)node * 64 + part * 4);
    float4 bv = *reinterpret_cast<const float4*>(b1 + part * 4);
    float4 hv;
    hv.x = fmaxf(sv.x * r + bv.x + qv.x, 0.f);
    hv.y = fmaxf(sv.y * r + bv.y + qv.y, 0.f);
    hv.z = fmaxf(sv.z * r + bv.z + qv.z, 0.f);
    hv.w = fmaxf(sv.w * r + bv.w + qv.w, 0.f);
    *reinterpret_cast<float4*>(g_h + (size_t)node * 64 + part * 4) = hv;
}

// ---------------------------------------------------------------------------
extern "C" void kernel_launch(void* const* d_in, const int* in_sizes, int n_in,
                              void* d_out, int out_size)
{
    const float* x   = (const float*)d_in[0];
    const int*   ei  = (const int*)  d_in[1];
    const float* Wl1 = (const float*)d_in[2];
    const float* Wr1 = (const float*)d_in[3];
    const float* b1  = (const float*)d_in[4];
    const float* Wl2 = (const float*)d_in[5];
    const float* Wr2 = (const float*)d_in[6];
    const float* b2  = (const float*)d_in[7];
    float* out = (float*)d_out;

    int N = in_sizes[0] / 128;
    int E = in_sizes[1] / 2;

    int egrid  = (E + 255) / 256;
    int ngrid  = (N + 255) / 256;
    int ggrid  = (N + 127) / 128;
    int hgrid  = (N * 16 + 255) / 256;
    int agrid  = (N * 32 + 255) / 256;
    int nb1    = (N + 511) / 512;          // scan1 blocks (<=256)

    zero_cnt_kernel<<<(N / 4 + 256) / 256, 256>>>(N);
    hist_kernel<<<egrid, 256>>>(ei, E);
    gemm_tc<1><<<ggrid, 256>>>(x, Wl1, Wr1, nullptr, nullptr, N);
    scan1_kernel<<<nb1, 512>>>(N);
    scan2_kernel<<<1, 256>>>(nb1);
    scan3_kernel<<<ngrid, 256>>>(N);
    fill_kernel<<<egrid, 256>>>(ei, E);
    agg_kernel<1><<<agrid, 256>>>(N);
    h_kernel<<<hgrid, 256>>>(b1, N);
    agg_kernel<2><<<agrid, 256>>>(N);
    gemm_tc<2><<<ggrid, 256>>>(nullptr, Wl2, Wr2, b2, out, N);
}

// round 8
// speedup vs baseline: 1.7045x; 1.0601x over previous
#include <cuda_runtime.h>
#include <cuda_bf16.h>
#include <cstdint>

// GraphSAGE 2-layer, CSR-pull aggregation (no feature atomics).
//   p1 = x @ W_l1^T, q1 = x @ W_r1^T     (GEMM1 tf32 tensor-core, pipelined)
//   CSR build: hist(dst) -> scan -> fill
//   agg1: h = relu( (sum_{src} p1[src]) / max(deg,1) + b1 + q1 )   (fused epilogue)
//   agg2: s2[n] = sum_{src} h[src]
//   out   = [s2/deg | h] @ [W_l2 | W_r2]^T + b2   (GEMM2 tf32 tensor-core, pipelined)
//
// __device__ globals referenced ONLY inside kernels.

#define NMAX 100000
#define EMAX 1600000

__device__ __align__(16) float g_p1    [(size_t)NMAX * 64];
__device__ __align__(16) float g_q1    [(size_t)NMAX * 64];
__device__ __align__(16) float g_h     [(size_t)NMAX * 64];
__device__ __align__(16) float g_s2    [(size_t)NMAX * 64];
__device__ __align__(16) int   g_cnt   [NMAX];
__device__ __align__(16) int   g_starts[NMAX];
__device__ __align__(16) int   g_cursor[NMAX];
__device__ __align__(16) int   g_bsum  [256];
__device__ __align__(16) int   g_boff  [256];
__device__ __align__(16) int   g_csrc  [EMAX];

// ---------------------------------------------------------------------------
// CSR build
// ---------------------------------------------------------------------------
__global__ void zero_cnt_kernel(int N) {
    int gid = blockIdx.x * 256 + threadIdx.x;
    if (gid * 4 < N) {
        int4 z = make_int4(0, 0, 0, 0);
        reinterpret_cast<int4*>(g_cnt)[gid] = z;
    }
}

__global__ void hist_kernel(const int* __restrict__ ei, int E) {
    int e = blockIdx.x * 256 + threadIdx.x;
    if (e < E) atomicAdd(&g_cnt[__ldg(ei + E + e)], 1);
}

__global__ void scan1_kernel(int N) {
    __shared__ int sm[512];
    int tid = threadIdx.x;
    int gid = blockIdx.x * 512 + tid;
    int v = (gid < N) ? g_cnt[gid] : 0;
    sm[tid] = v;
    __syncthreads();
#pragma unroll
    for (int off = 1; off < 512; off <<= 1) {
        int t = (tid >= off) ? sm[tid - off] : 0;
        __syncthreads();
        sm[tid] += t;
        __syncthreads();
    }
    if (gid < N) g_starts[gid] = sm[tid] - v;
    if (tid == 511) g_bsum[blockIdx.x] = sm[511];
}

__global__ void scan2_kernel(int nb) {
    __shared__ int sm[256];
    int tid = threadIdx.x;
    int v = (tid < nb) ? g_bsum[tid] : 0;
    sm[tid] = v;
    __syncthreads();
#pragma unroll
    for (int off = 1; off < 256; off <<= 1) {
        int t = (tid >= off) ? sm[tid - off] : 0;
        __syncthreads();
        sm[tid] += t;
        __syncthreads();
    }
    if (tid < nb) g_boff[tid] = sm[tid] - v;
}

__global__ void scan3_kernel(int N) {
    int gid = blockIdx.x * 256 + threadIdx.x;
    if (gid < N) {
        int s = g_starts[gid] + g_boff[gid >> 9];
        g_starts[gid] = s;
        g_cursor[gid] = s;
    }
}

__global__ void fill_kernel(const int* __restrict__ ei, int E) {
    int e = blockIdx.x * 256 + threadIdx.x;
    if (e < E) {
        int s = __ldg(ei + e);
        int d = __ldg(ei + E + e);
        int slot = atomicAdd(&g_cursor[d], 1);
        g_csrc[slot] = s;
    }
}

// ---------------------------------------------------------------------------
// aggregate: one warp per dst node, lanes hold 2 floats each, 2-edge unroll
// LAYER 1: feat = g_p1; fused epilogue writes g_h = relu(acc*r + b1 + q1)
// LAYER 2: feat = g_h -> g_s2
// ---------------------------------------------------------------------------
template <int LAYER>
__global__ void agg_kernel(const float* __restrict__ b1, int N) {
    int w = (blockIdx.x * 256 + threadIdx.x) >> 5;
    if (w >= N) return;
    int lane = threadIdx.x & 31;
    int beg = g_starts[w];
    int end = beg + g_cnt[w];
    const float* feat = (LAYER == 1) ? g_p1 : g_h;
    float2 acc = make_float2(0.f, 0.f);
    int j = beg;
    for (; j + 2 <= end; j += 2) {
        int s0 = __ldg(g_csrc + j);
        int s1 = __ldg(g_csrc + j + 1);
        float2 a = *reinterpret_cast<const float2*>(feat + (size_t)s0 * 64 + lane * 2);
        float2 b = *reinterpret_cast<const float2*>(feat + (size_t)s1 * 64 + lane * 2);
        acc.x += a.x + b.x;
        acc.y += a.y + b.y;
    }
    if (j < end) {
        int s0 = __ldg(g_csrc + j);
        float2 a = *reinterpret_cast<const float2*>(feat + (size_t)s0 * 64 + lane * 2);
        acc.x += a.x;
        acc.y += a.y;
    }
    if (LAYER == 1) {
        float r = 1.0f / fmaxf((float)(end - beg), 1.0f);
        float2 qv = *reinterpret_cast<const float2*>(g_q1 + (size_t)w * 64 + lane * 2);
        float2 bv = *reinterpret_cast<const float2*>(b1 + lane * 2);
        float2 hv;
        hv.x = fmaxf(acc.x * r + bv.x + qv.x, 0.f);
        hv.y = fmaxf(acc.y * r + bv.y + qv.y, 0.f);
        *reinterpret_cast<float2*>(g_h + (size_t)w * 64 + lane * 2) = hv;
    } else {
        *reinterpret_cast<float2*>(g_s2 + (size_t)w * 64 + lane * 2) = acc;
    }
}

// ---------------------------------------------------------------------------
// tf32 tensor-core GEMM, register-double-buffered k-chunk pipeline.
// Block: 256 threads (8 warps, 4x2), tile 128x128, K chunked by 32.
// smem paired-k layout: koff(kl) -> (k, k+4) adjacent; LDC = 40 (40 KB total).
// ---------------------------------------------------------------------------
#define LDC 40

__device__ __forceinline__ uint32_t f2tf32(float f) {
    uint32_t o; asm("cvt.rna.tf32.f32 %0, %1;" : "=r"(o) : "f"(f)); return o;
}
__device__ __forceinline__ int koff(int kl) {
    return (kl & ~7) + ((kl & 3) << 1) + ((kl >> 2) & 1);
}

#define MMA4(c, a, b) asm volatile( \
  "mma.sync.aligned.m16n8k8.row.col.f32.tf32.tf32.f32 " \
  "{%0,%1,%2,%3},{%4,%5,%6,%7},{%8,%9},{%0,%1,%2,%3};" \
  : "+f"(c[0]), "+f"(c[1]), "+f"(c[2]), "+f"(c[3]) \
  : "r"(a[0]), "r"(a[1]), "r"(a[2]), "r"(a[3]), "r"(b.x), "r"(b.y))

// MODE 1: A = x [N,128]; B rows: n<64 -> Wl1, else Wr1; writes g_p1 / g_q1
// MODE 2: A cols 0..63 = s2 * (1/max(cnt,1)), 64..127 = h; B: k<64 -> Wl2 else Wr2; +bias
template<int MODE>
__global__ __launch_bounds__(256, 2) void gemm_tc(
    const float* __restrict__ x,
    const float* __restrict__ Wl, const float* __restrict__ Wr,
    const float* __restrict__ bias, float* __restrict__ outp, int N)
{
    __shared__ uint32_t As[128 * LDC];
    __shared__ uint32_t Bs[128 * LDC];
    const int tid  = threadIdx.x;
    const int m0   = blockIdx.x * 128;
    const int lane = tid & 31, warp = tid >> 5;
    const int g    = lane >> 2, t = lane & 3;
    const int rm   = (warp >> 1) * 32;
    const int cn   = (warp & 1) * 64;

    float4 va[4], vb[4];

    // loadA/loadB: fetch one 32-wide k-chunk into registers
    auto loadA = [&](int kc) {
#pragma unroll
        for (int it = 0; it < 4; it++) {
            int f = tid + it * 256;
            int row = f >> 3, q = f & 7;
            int gm = m0 + row;
            float4 v = make_float4(0.f, 0.f, 0.f, 0.f);
            if (MODE == 1) {
                if (gm < N)
                    v = *reinterpret_cast<const float4*>(x + (size_t)gm * 128 + kc + q * 4);
            } else {
                if (gm < N) {
                    if (kc < 64) {
                        v = *reinterpret_cast<const float4*>(g_s2 + (size_t)gm * 64 + kc + q * 4);
                        float r = 1.0f / fmaxf((float)g_cnt[gm], 1.0f);
                        v.x *= r; v.y *= r; v.z *= r; v.w *= r;
                    } else {
                        v = *reinterpret_cast<const float4*>(g_h + (size_t)gm * 64 + (kc - 64) + q * 4);
                    }
                }
            }
            va[it] = v;
        }
    };
    auto loadB = [&](int kc) {
#pragma unroll
        for (int it = 0; it < 4; it++) {
            int f = tid + it * 256;
            int n = f >> 3, q = f & 7;
            const float* src;
            if (MODE == 1)
                src = (n < 64) ? (Wl + (size_t)n * 128 + kc + q * 4)
                               : (Wr + (size_t)(n - 64) * 128 + kc + q * 4);
            else
                src = ((kc < 64) ? (Wl + (size_t)n * 64 + kc)
                                 : (Wr + (size_t)n * 64 + (kc - 64))) + q * 4;
            vb[it] = *reinterpret_cast<const float4*>(src);
        }
    };

    float acc[2][8][4];
#pragma unroll
    for (int i = 0; i < 2; i++)
#pragma unroll
        for (int j = 0; j < 8; j++)
#pragma unroll
            for (int q = 0; q < 4; q++) acc[i][j][q] = 0.f;

    loadA(0); loadB(0);

#pragma unroll
    for (int kc = 0; kc < 128; kc += 32) {
        // ---- STS current chunk (regs -> smem, tf32 convert) ----
#pragma unroll
        for (int it = 0; it < 4; it++) {
            int f = tid + it * 256;
            int row = f >> 3, q = f & 7;
            int kl = q * 4;
            uint32_t* dstA = As + row * LDC;
            dstA[koff(kl + 0)] = f2tf32(va[it].x);
            dstA[koff(kl + 1)] = f2tf32(va[it].y);
            dstA[koff(kl + 2)] = f2tf32(va[it].z);
            dstA[koff(kl + 3)] = f2tf32(va[it].w);
            uint32_t* dstB = Bs + row * LDC;
            dstB[koff(kl + 0)] = f2tf32(vb[it].x);
            dstB[koff(kl + 1)] = f2tf32(vb[it].y);
            dstB[koff(kl + 2)] = f2tf32(vb[it].z);
            dstB[koff(kl + 3)] = f2tf32(vb[it].w);
        }
        __syncthreads();
        // ---- prefetch next chunk (LDG latency hides behind MMA below) ----
        if (kc < 96) { loadA(kc + 32); loadB(kc + 32); }
        // ---- compute: 4 k-steps of m16n8k8 ----
#pragma unroll
        for (int s = 0; s < 4; s++) {
            uint32_t a[2][4];
#pragma unroll
            for (int mt = 0; mt < 2; mt++) {
                int m = rm + mt * 16 + g;
                uint2 lo = *reinterpret_cast<const uint2*>(As + m * LDC + s * 8 + t * 2);
                uint2 hi = *reinterpret_cast<const uint2*>(As + (m + 8) * LDC + s * 8 + t * 2);
                a[mt][0] = lo.x; a[mt][1] = hi.x; a[mt][2] = lo.y; a[mt][3] = hi.y;
            }
#pragma unroll
            for (int nt = 0; nt < 8; nt++) {
                uint2 b = *reinterpret_cast<const uint2*>(Bs + (cn + nt * 8 + g) * LDC + s * 8 + t * 2);
                MMA4(acc[0][nt], a[0], b);
                MMA4(acc[1][nt], a[1], b);
            }
        }
        __syncthreads();
    }
    // ---- epilogue ----
#pragma unroll
    for (int mt = 0; mt < 2; mt++) {
#pragma unroll
        for (int nt = 0; nt < 8; nt++) {
            int row = m0 + rm + mt * 16 + g;
            int col = cn + nt * 8 + t * 2;
            if (MODE == 1) {
                float* buf = (cn == 0) ? g_p1 : g_q1;
                int c64 = nt * 8 + t * 2;
                if (row < N)
                    *reinterpret_cast<float2*>(buf + (size_t)row * 64 + c64) =
                        make_float2(acc[mt][nt][0], acc[mt][nt][1]);
                if (row + 8 < N)
                    *reinterpret_cast<float2*>(buf + (size_t)(row + 8) * 64 + c64) =
                        make_float2(acc[mt][nt][2], acc[mt][nt][3]);
            } else {
                float2 bb = *reinterpret_cast<const float2*>(bias + col);
                if (row < N)
                    *reinterpret_cast<float2*>(outp + (size_t)row * 128 + col) =
                        make_float2(acc[mt][nt][0] + bb.x, acc[mt][nt][1] + bb.y);
                if (row + 8 < N)
                    *reinterpret_cast<float2*>(outp + (size_t)(row + 8) * 128 + col) =
                        make_float2(acc[mt][nt][2] + bb.x, acc[mt][nt][3] + bb.y);
            }
        }
    }
}

// ---------------------------------------------------------------------------
extern "C" void kernel_launch(void* const* d_in, const int* in_sizes, int n_in,
                              void* d_out, int out_size)
{
    const float* x   = (const float*)d_in[0];
    const int*   ei  = (const int*)  d_in[1];
    const float* Wl1 = (const float*)d_in[2];
    const float* Wr1 = (const float*)d_in[3];
    const float* b1  = (const float*)d_in[4];
    const float* Wl2 = (const float*)d_in[5];
    const float* Wr2 = (const float*)d_in[6];
    const float* b2  = (const float*)d_in[7];
    float* out = (float*)d_out;

    int N = in_sizes[0] / 128;
    int E = in_sizes[1] / 2;

    int egrid  = (E + 255) / 256;
    int ngrid  = (N + 255) / 256;
    int ggrid  = (N + 127) / 128;
    int agrid  = (N * 32 + 255) / 256;
    int nb1    = (N + 511) / 512;

    zero_cnt_kernel<<<(N / 4 + 256) / 256, 256>>>(N);
    hist_kernel<<<egrid, 256>>>(ei, E);
    gemm_tc<1><<<ggrid, 256>>>(x, Wl1, Wr1, nullptr, nullptr, N);
    scan1_kernel<<<nb1, 512>>>(N);
    scan2_kernel<<<1, 256>>>(nb1);
    scan3_kernel<<<ngrid, 256>>>(N);
    fill_kernel<<<egrid, 256>>>(ei, E);
    agg_kernel<1><<<agrid, 256>>>(b1, N);
    agg_kernel<2><<<agrid, 256>>>(nullptr, N);
    gemm_tc<2><<<ggrid, 256>>>(nullptr, Wl2, Wr2, b2, out, N);
}

// round 9
// speedup vs baseline: 1.7205x; 1.0093x over previous
#include <cuda_runtime.h>
#include <cuda_fp16.h>
#include <cstdint>

// GraphSAGE 2-layer, CSR-pull aggregation, fp16 gathered features.
//   p1(fp16) = x @ W_l1^T, q1(fp32) = x @ W_r1^T   (GEMM1 tf32 TC)
//   CSR build: hist(dst) -> scan -> fill
//   agg1: h(fp16) = relu( (sum p1[src]) / max(deg,1) + b1 + q1 )  [fp32 accum]
//   agg2: s2(fp32) = sum h[src]                                    [fp32 accum]
//   out  = [s2/deg | h] @ [W_l2 | W_r2]^T + b2     (GEMM2 tf32 TC; fp16->tf32 exact)
//
// __device__ globals referenced ONLY inside kernels.

#define NMAX 100000
#define EMAX 1600000

__device__ __align__(16) __half2 g_p1h [(size_t)NMAX * 32];
__device__ __align__(16) float   g_q1  [(size_t)NMAX * 64];
__device__ __align__(16) __half2 g_hh  [(size_t)NMAX * 32];
__device__ __align__(16) float   g_s2  [(size_t)NMAX * 64];
__device__ __align__(16) int   g_cnt   [NMAX];
__device__ __align__(16) int   g_starts[NMAX];
__device__ __align__(16) int   g_cursor[NMAX];
__device__ __align__(16) int   g_bsum  [256];
__device__ __align__(16) int   g_boff  [256];
__device__ __align__(16) int   g_csrc  [EMAX];

// ---------------------------------------------------------------------------
// CSR build
// ---------------------------------------------------------------------------
__global__ void zero_cnt_kernel(int N) {
    int gid = blockIdx.x * 256 + threadIdx.x;
    if (gid * 4 < N) {
        int4 z = make_int4(0, 0, 0, 0);
        reinterpret_cast<int4*>(g_cnt)[gid] = z;
    }
}

__global__ void hist_kernel(const int* __restrict__ ei, int E) {
    int e = blockIdx.x * 256 + threadIdx.x;
    if (e < E) atomicAdd(&g_cnt[__ldg(ei + E + e)], 1);
}

__global__ void scan1_kernel(int N) {
    __shared__ int sm[512];
    int tid = threadIdx.x;
    int gid = blockIdx.x * 512 + tid;
    int v = (gid < N) ? g_cnt[gid] : 0;
    sm[tid] = v;
    __syncthreads();
#pragma unroll
    for (int off = 1; off < 512; off <<= 1) {
        int t = (tid >= off) ? sm[tid - off] : 0;
        __syncthreads();
        sm[tid] += t;
        __syncthreads();
    }
    if (gid < N) g_starts[gid] = sm[tid] - v;
    if (tid == 511) g_bsum[blockIdx.x] = sm[511];
}

__global__ void scan2_kernel(int nb) {
    __shared__ int sm[256];
    int tid = threadIdx.x;
    int v = (tid < nb) ? g_bsum[tid] : 0;
    sm[tid] = v;
    __syncthreads();
#pragma unroll
    for (int off = 1; off < 256; off <<= 1) {
        int t = (tid >= off) ? sm[tid - off] : 0;
        __syncthreads();
        sm[tid] += t;
        __syncthreads();
    }
    if (tid < nb) g_boff[tid] = sm[tid] - v;
}

__global__ void scan3_kernel(int N) {
    int gid = blockIdx.x * 256 + threadIdx.x;
    if (gid < N) {
        int s = g_starts[gid] + g_boff[gid >> 9];
        g_starts[gid] = s;
        g_cursor[gid] = s;
    }
}

__global__ void fill_kernel(const int* __restrict__ ei, int E) {
    int e = blockIdx.x * 256 + threadIdx.x;
    if (e < E) {
        int s = __ldg(ei + e);
        int d = __ldg(ei + E + e);
        int slot = atomicAdd(&g_cursor[d], 1);
        g_csrc[slot] = s;
    }
}

// ---------------------------------------------------------------------------
// aggregate: one warp per dst node; lane holds dims (2*lane, 2*lane+1).
// fp16 gathers (one __half2 per lane per edge), fp32 accumulation, x4 unroll.
// LAYER 1: g_p1h -> h = relu(acc*r + b1 + q1) stored fp16 (g_hh)
// LAYER 2: g_hh  -> s2 fp32
// ---------------------------------------------------------------------------
template <int LAYER>
__global__ void agg_kernel(const float* __restrict__ b1, int N) {
    int w = (blockIdx.x * 256 + threadIdx.x) >> 5;
    if (w >= N) return;
    int lane = threadIdx.x & 31;
    int beg = g_starts[w];
    int end = beg + g_cnt[w];
    const __half2* feat = (LAYER == 1) ? g_p1h : g_hh;
    float2 acc = make_float2(0.f, 0.f);
    int j = beg;
    for (; j + 4 <= end; j += 4) {
        int s0 = __ldg(g_csrc + j);
        int s1 = __ldg(g_csrc + j + 1);
        int s2 = __ldg(g_csrc + j + 2);
        int s3 = __ldg(g_csrc + j + 3);
        float2 a = __half22float2(__ldg(feat + (size_t)s0 * 32 + lane));
        float2 b = __half22float2(__ldg(feat + (size_t)s1 * 32 + lane));
        float2 c = __half22float2(__ldg(feat + (size_t)s2 * 32 + lane));
        float2 d = __half22float2(__ldg(feat + (size_t)s3 * 32 + lane));
        acc.x += (a.x + b.x) + (c.x + d.x);
        acc.y += (a.y + b.y) + (c.y + d.y);
    }
    for (; j < end; j++) {
        int s0 = __ldg(g_csrc + j);
        float2 a = __half22float2(__ldg(feat + (size_t)s0 * 32 + lane));
        acc.x += a.x;
        acc.y += a.y;
    }
    if (LAYER == 1) {
        float r = 1.0f / fmaxf((float)(end - beg), 1.0f);
        float2 qv = *reinterpret_cast<const float2*>(g_q1 + (size_t)w * 64 + lane * 2);
        float2 bv = *reinterpret_cast<const float2*>(b1 + lane * 2);
        float2 hv;
        hv.x = fmaxf(acc.x * r + bv.x + qv.x, 0.f);
        hv.y = fmaxf(acc.y * r + bv.y + qv.y, 0.f);
        g_hh[(size_t)w * 32 + lane] = __float22half2_rn(hv);
    } else {
        *reinterpret_cast<float2*>(g_s2 + (size_t)w * 64 + lane * 2) = acc;
    }
}

// ---------------------------------------------------------------------------
// tf32 tensor-core GEMM, register-double-buffered k-chunk pipeline.
// Block: 256 threads (8 warps, 4x2), tile 128x128, K chunked by 32.
// smem paired-k layout: koff(kl) -> (k, k+4) adjacent; LDC = 40 (40 KB total).
// ---------------------------------------------------------------------------
#define LDC 40

__device__ __forceinline__ uint32_t f2tf32(float f) {
    uint32_t o; asm("cvt.rna.tf32.f32 %0, %1;" : "=r"(o) : "f"(f)); return o;
}
__device__ __forceinline__ int koff(int kl) {
    return (kl & ~7) + ((kl & 3) << 1) + ((kl >> 2) & 1);
}

#define MMA4(c, a, b) asm volatile( \
  "mma.sync.aligned.m16n8k8.row.col.f32.tf32.tf32.f32 " \
  "{%0,%1,%2,%3},{%4,%5,%6,%7},{%8,%9},{%0,%1,%2,%3};" \
  : "+f"(c[0]), "+f"(c[1]), "+f"(c[2]), "+f"(c[3]) \
  : "r"(a[0]), "r"(a[1]), "r"(a[2]), "r"(a[3]), "r"(b.x), "r"(b.y))

// MODE 1: A = x [N,128]; B rows: n<64 -> Wl1, else Wr1; writes g_p1h(fp16)/g_q1(fp32)
// MODE 2: A cols 0..63 = s2 * (1/max(cnt,1)) [fp32], 64..127 = h [fp16->tf32 exact];
//         B: k<64 -> Wl2 else Wr2; +bias; writes outp
template<int MODE>
__global__ __launch_bounds__(256, 2) void gemm_tc(
    const float* __restrict__ x,
    const float* __restrict__ Wl, const float* __restrict__ Wr,
    const float* __restrict__ bias, float* __restrict__ outp, int N)
{
    __shared__ uint32_t As[128 * LDC];
    __shared__ uint32_t Bs[128 * LDC];
    const int tid  = threadIdx.x;
    const int m0   = blockIdx.x * 128;
    const int lane = tid & 31, warp = tid >> 5;
    const int g    = lane >> 2, t = lane & 3;
    const int rm   = (warp >> 1) * 32;
    const int cn   = (warp & 1) * 64;

    float4 va[4], vb[4];

    auto loadA = [&](int kc) {
#pragma unroll
        for (int it = 0; it < 4; it++) {
            int f = tid + it * 256;
            int row = f >> 3, q = f & 7;
            int gm = m0 + row;
            float4 v = make_float4(0.f, 0.f, 0.f, 0.f);
            if (MODE == 1) {
                if (gm < N)
                    v = *reinterpret_cast<const float4*>(x + (size_t)gm * 128 + kc + q * 4);
            } else {
                if (gm < N) {
                    if (kc < 64) {
                        v = *reinterpret_cast<const float4*>(g_s2 + (size_t)gm * 64 + kc + q * 4);
                        float r = 1.0f / fmaxf((float)g_cnt[gm], 1.0f);
                        v.x *= r; v.y *= r; v.z *= r; v.w *= r;
                    } else {
                        // fp16 h: 4 halves = 2 x __half2
                        size_t idx = (size_t)gm * 32 + ((kc - 64) >> 1) + q * 2;
                        float2 f0 = __half22float2(g_hh[idx]);
                        float2 f1 = __half22float2(g_hh[idx + 1]);
                        v = make_float4(f0.x, f0.y, f1.x, f1.y);
                    }
                }
            }
            va[it] = v;
        }
    };
    auto loadB = [&](int kc) {
#pragma unroll
        for (int it = 0; it < 4; it++) {
            int f = tid + it * 256;
            int n = f >> 3, q = f & 7;
            const float* src;
            if (MODE == 1)
                src = (n < 64) ? (Wl + (size_t)n * 128 + kc + q * 4)
                               : (Wr + (size_t)(n - 64) * 128 + kc + q * 4);
            else
                src = ((kc < 64) ? (Wl + (size_t)n * 64 + kc)
                                 : (Wr + (size_t)n * 64 + (kc - 64))) + q * 4;
            vb[it] = *reinterpret_cast<const float4*>(src);
        }
    };

    float acc[2][8][4];
#pragma unroll
    for (int i = 0; i < 2; i++)
#pragma unroll
        for (int j = 0; j < 8; j++)
#pragma unroll
            for (int q = 0; q < 4; q++) acc[i][j][q] = 0.f;

    loadA(0); loadB(0);

#pragma unroll
    for (int kc = 0; kc < 128; kc += 32) {
        // ---- STS current chunk (regs -> smem, tf32 convert) ----
#pragma unroll
        for (int it = 0; it < 4; it++) {
            int f = tid + it * 256;
            int row = f >> 3, q = f & 7;
            int kl = q * 4;
            uint32_t* dstA = As + row * LDC;
            dstA[koff(kl + 0)] = f2tf32(va[it].x);
            dstA[koff(kl + 1)] = f2tf32(va[it].y);
            dstA[koff(kl + 2)] = f2tf32(va[it].z);
            dstA[koff(kl + 3)] = f2tf32(va[it].w);
            uint32_t* dstB = Bs + row * LDC;
            dstB[koff(kl + 0)] = f2tf32(vb[it].x);
            dstB[koff(kl + 1)] = f2tf32(vb[it].y);
            dstB[koff(kl + 2)] = f2tf32(vb[it].z);
            dstB[koff(kl + 3)] = f2tf32(vb[it].w);
        }
        __syncthreads();
        // ---- prefetch next chunk ----
        if (kc < 96) { loadA(kc + 32); loadB(kc + 32); }
        // ---- compute: 4 k-steps of m16n8k8 ----
#pragma unroll
        for (int s = 0; s < 4; s++) {
            uint32_t a[2][4];
#pragma unroll
            for (int mt = 0; mt < 2; mt++) {
                int m = rm + mt * 16 + g;
                uint2 lo = *reinterpret_cast<const uint2*>(As + m * LDC + s * 8 + t * 2);
                uint2 hi = *reinterpret_cast<const uint2*>(As + (m + 8) * LDC + s * 8 + t * 2);
                a[mt][0] = lo.x; a[mt][1] = hi.x; a[mt][2] = lo.y; a[mt][3] = hi.y;
            }
#pragma unroll
            for (int nt = 0; nt < 8; nt++) {
                uint2 b = *reinterpret_cast<const uint2*>(Bs + (cn + nt * 8 + g) * LDC + s * 8 + t * 2);
                MMA4(acc[0][nt], a[0], b);
                MMA4(acc[1][nt], a[1], b);
            }
        }
        __syncthreads();
    }
    // ---- epilogue ----
#pragma unroll
    for (int mt = 0; mt < 2; mt++) {
#pragma unroll
        for (int nt = 0; nt < 8; nt++) {
            int row = m0 + rm + mt * 16 + g;
            int col = cn + nt * 8 + t * 2;
            if (MODE == 1) {
                int c64 = nt * 8 + t * 2;
                if (cn == 0) {
                    // p1 -> fp16
                    if (row < N)
                        g_p1h[(size_t)row * 32 + (c64 >> 1)] =
                            __floats2half2_rn(acc[mt][nt][0], acc[mt][nt][1]);
                    if (row + 8 < N)
                        g_p1h[(size_t)(row + 8) * 32 + (c64 >> 1)] =
                            __floats2half2_rn(acc[mt][nt][2], acc[mt][nt][3]);
                } else {
                    // q1 -> fp32
                    if (row < N)
                        *reinterpret_cast<float2*>(g_q1 + (size_t)row * 64 + c64) =
                            make_float2(acc[mt][nt][0], acc[mt][nt][1]);
                    if (row + 8 < N)
                        *reinterpret_cast<float2*>(g_q1 + (size_t)(row + 8) * 64 + c64) =
                            make_float2(acc[mt][nt][2], acc[mt][nt][3]);
                }
            } else {
                float2 bb = *reinterpret_cast<const float2*>(bias + col);
                if (row < N)
                    *reinterpret_cast<float2*>(outp + (size_t)row * 128 + col) =
                        make_float2(acc[mt][nt][0] + bb.x, acc[mt][nt][1] + bb.y);
                if (row + 8 < N)
                    *reinterpret_cast<float2*>(outp + (size_t)(row + 8) * 128 + col) =
                        make_float2(acc[mt][nt][2] + bb.x, acc[mt][nt][3] + bb.y);
            }
        }
    }
}

// ---------------------------------------------------------------------------
extern "C" void kernel_launch(void* const* d_in, const int* in_sizes, int n_in,
                              void* d_out, int out_size)
{
    const float* x   = (const float*)d_in[0];
    const int*   ei  = (const int*)  d_in[1];
    const float* Wl1 = (const float*)d_in[2];
    const float* Wr1 = (const float*)d_in[3];
    const float* b1  = (const float*)d_in[4];
    const float* Wl2 = (const float*)d_in[5];
    const float* Wr2 = (const float*)d_in[6];
    const float* b2  = (const float*)d_in[7];
    float* out = (float*)d_out;

    int N = in_sizes[0] / 128;
    int E = in_sizes[1] / 2;

    int egrid  = (E + 255) / 256;
    int ngrid  = (N + 255) / 256;
    int ggrid  = (N + 127) / 128;
    int agrid  = (N * 32 + 255) / 256;
    int nb1    = (N + 511) / 512;

    zero_cnt_kernel<<<(N / 4 + 256) / 256, 256>>>(N);
    hist_kernel<<<egrid, 256>>>(ei, E);
    gemm_tc<1><<<ggrid, 256>>>(x, Wl1, Wr1, nullptr, nullptr, N);
    scan1_kernel<<<nb1, 512>>>(N);
    scan2_kernel<<<1, 256>>>(nb1);
    scan3_kernel<<<ngrid, 256>>>(N);
    fill_kernel<<<egrid, 256>>>(ei, E);
    agg_kernel<1><<<agrid, 256>>>(b1, N);
    agg_kernel<2><<<agrid, 256>>>(nullptr, N);
    gemm_tc<2><<<ggrid, 256>>>(nullptr, Wl2, Wr2, b2, out, N);
}

// round 10
// speedup vs baseline: 1.8169x; 1.0561x over previous
#include <cuda_runtime.h>
#include <cuda_fp16.h>
#include <cstdint>

// GraphSAGE 2-layer, CSR-pull aggregation, fp16 gathered features,
// two-stream overlap: CSR build || GEMM1.
//   p1(fp16) = x @ W_l1^T, q1(fp32) = x @ W_r1^T   (GEMM1 tf32 TC)
//   CSR build: hist(dst) -> scan -> fill            (concurrent with GEMM1)
//   agg1: h(fp16) = relu( (sum p1[src]) / max(deg,1) + b1 + q1 )  [fp32 accum]
//   agg2: s2(fp32) = sum h[src]
//   out  = [s2/deg | h] @ [W_l2 | W_r2]^T + b2     (GEMM2 tf32 TC)
//
// __device__ globals referenced ONLY inside kernels.

#define NMAX 100000
#define EMAX 1600000

__device__ __align__(16) __half2 g_p1h [(size_t)NMAX * 32];
__device__ __align__(16) float   g_q1  [(size_t)NMAX * 64];
__device__ __align__(16) __half2 g_hh  [(size_t)NMAX * 32];
__device__ __align__(16) float   g_s2  [(size_t)NMAX * 64];
__device__ __align__(16) int   g_cnt   [NMAX];
__device__ __align__(16) int   g_starts[NMAX];
__device__ __align__(16) int   g_cursor[NMAX];
__device__ __align__(16) int   g_bsum  [256];
__device__ __align__(16) int   g_csrc  [EMAX];

// ---------------------------------------------------------------------------
// CSR build
// ---------------------------------------------------------------------------
__global__ void zero_cnt_kernel(int N) {
    int gid = blockIdx.x * 256 + threadIdx.x;
    if (gid * 4 < N) {
        int4 z = make_int4(0, 0, 0, 0);
        reinterpret_cast<int4*>(g_cnt)[gid] = z;
    }
}

__global__ void hist_kernel(const int* __restrict__ ei, int E) {
    int e = blockIdx.x * 256 + threadIdx.x;
    if (e < E) atomicAdd(&g_cnt[__ldg(ei + E + e)], 1);
}

__global__ void scan1_kernel(int N) {
    __shared__ int sm[512];
    int tid = threadIdx.x;
    int gid = blockIdx.x * 512 + tid;
    int v = (gid < N) ? g_cnt[gid] : 0;
    sm[tid] = v;
    __syncthreads();
#pragma unroll
    for (int off = 1; off < 512; off <<= 1) {
        int t = (tid >= off) ? sm[tid - off] : 0;
        __syncthreads();
        sm[tid] += t;
        __syncthreads();
    }
    if (gid < N) g_starts[gid] = sm[tid] - v;
    if (tid == 511) g_bsum[blockIdx.x] = sm[511];
}

// scan23: each block redundantly scans the (<=256) block sums in smem,
// then applies offsets to its 256 node slots; also inits cursor.
__global__ void scan23_kernel(int N, int nb) {
    __shared__ int sm[256];
    int tid = threadIdx.x;
    int v = (tid < nb) ? g_bsum[tid] : 0;
    sm[tid] = v;
    __syncthreads();
#pragma unroll
    for (int off = 1; off < 256; off <<= 1) {
        int t = (tid >= off) ? sm[tid - off] : 0;
        __syncthreads();
        sm[tid] += t;
        __syncthreads();
    }
    sm[tid] -= v;            // exclusive
    __syncthreads();
    int gid = blockIdx.x * 256 + tid;
    if (gid < N) {
        int s = g_starts[gid] + sm[gid >> 9];
        g_starts[gid] = s;
        g_cursor[gid] = s;
    }
}

__global__ void fill_kernel(const int* __restrict__ ei, int E) {
    int e = blockIdx.x * 256 + threadIdx.x;
    if (e < E) {
        int s = __ldg(ei + e);
        int d = __ldg(ei + E + e);
        int slot = atomicAdd(&g_cursor[d], 1);
        g_csrc[slot] = s;
    }
}

// ---------------------------------------------------------------------------
// aggregate: one warp per dst node; lane holds dims (2*lane, 2*lane+1).
// fp16 gathers, fp32 accumulation, x4 unroll.
// LAYER 1: g_p1h -> h = relu(acc*r + b1 + q1) stored fp16 (g_hh)
// LAYER 2: g_hh  -> s2 fp32
// ---------------------------------------------------------------------------
template <int LAYER>
__global__ void agg_kernel(const float* __restrict__ b1, int N) {
    int w = (blockIdx.x * 256 + threadIdx.x) >> 5;
    if (w >= N) return;
    int lane = threadIdx.x & 31;
    int beg = g_starts[w];
    int end = beg + g_cnt[w];
    const __half2* feat = (LAYER == 1) ? g_p1h : g_hh;
    float2 acc = make_float2(0.f, 0.f);
    int j = beg;
    for (; j + 4 <= end; j += 4) {
        int s0 = __ldg(g_csrc + j);
        int s1 = __ldg(g_csrc + j + 1);
        int s2 = __ldg(g_csrc + j + 2);
        int s3 = __ldg(g_csrc + j + 3);
        float2 a = __half22float2(__ldg(feat + (size_t)s0 * 32 + lane));
        float2 b = __half22float2(__ldg(feat + (size_t)s1 * 32 + lane));
        float2 c = __half22float2(__ldg(feat + (size_t)s2 * 32 + lane));
        float2 d = __half22float2(__ldg(feat + (size_t)s3 * 32 + lane));
        acc.x += (a.x + b.x) + (c.x + d.x);
        acc.y += (a.y + b.y) + (c.y + d.y);
    }
    for (; j < end; j++) {
        int s0 = __ldg(g_csrc + j);
        float2 a = __half22float2(__ldg(feat + (size_t)s0 * 32 + lane));
        acc.x += a.x;
        acc.y += a.y;
    }
    if (LAYER == 1) {
        float r = 1.0f / fmaxf((float)(end - beg), 1.0f);
        float2 qv = *reinterpret_cast<const float2*>(g_q1 + (size_t)w * 64 + lane * 2);
        float2 bv = *reinterpret_cast<const float2*>(b1 + lane * 2);
        float2 hv;
        hv.x = fmaxf(acc.x * r + bv.x + qv.x, 0.f);
        hv.y = fmaxf(acc.y * r + bv.y + qv.y, 0.f);
        g_hh[(size_t)w * 32 + lane] = __float22half2_rn(hv);
    } else {
        *reinterpret_cast<float2*>(g_s2 + (size_t)w * 64 + lane * 2) = acc;
    }
}

// ---------------------------------------------------------------------------
// tf32 tensor-core GEMM, register-double-buffered k-chunk pipeline.
// Block: 256 threads (8 warps, 4x2), tile 128x128, K chunked by 32.
// smem paired-k layout: koff(kl) -> (k, k+4) adjacent; LDC = 40 (40 KB total).
// ---------------------------------------------------------------------------
#define LDC 40

__device__ __forceinline__ uint32_t f2tf32(float f) {
    uint32_t o; asm("cvt.rna.tf32.f32 %0, %1;" : "=r"(o) : "f"(f)); return o;
}
__device__ __forceinline__ int koff(int kl) {
    return (kl & ~7) + ((kl & 3) << 1) + ((kl >> 2) & 1);
}

#define MMA4(c, a, b) asm volatile( \
  "mma.sync.aligned.m16n8k8.row.col.f32.tf32.tf32.f32 " \
  "{%0,%1,%2,%3},{%4,%5,%6,%7},{%8,%9},{%0,%1,%2,%3};" \
  : "+f"(c[0]), "+f"(c[1]), "+f"(c[2]), "+f"(c[3]) \
  : "r"(a[0]), "r"(a[1]), "r"(a[2]), "r"(a[3]), "r"(b.x), "r"(b.y))

// MODE 1: A = x [N,128]; B rows: n<64 -> Wl1, else Wr1; writes g_p1h(fp16)/g_q1(fp32)
// MODE 2: A cols 0..63 = s2 * (1/max(cnt,1)) [fp32], 64..127 = h [fp16->tf32 exact];
//         B: k<64 -> Wl2 else Wr2; +bias; writes outp
template<int MODE>
__global__ __launch_bounds__(256, 2) void gemm_tc(
    const float* __restrict__ x,
    const float* __restrict__ Wl, const float* __restrict__ Wr,
    const float* __restrict__ bias, float* __restrict__ outp, int N)
{
    __shared__ uint32_t As[128 * LDC];
    __shared__ uint32_t Bs[128 * LDC];
    const int tid  = threadIdx.x;
    const int m0   = blockIdx.x * 128;
    const int lane = tid & 31, warp = tid >> 5;
    const int g    = lane >> 2, t = lane & 3;
    const int rm   = (warp >> 1) * 32;
    const int cn   = (warp & 1) * 64;

    float4 va[4], vb[4];

    auto loadA = [&](int kc) {
#pragma unroll
        for (int it = 0; it < 4; it++) {
            int f = tid + it * 256;
            int row = f >> 3, q = f & 7;
            int gm = m0 + row;
            float4 v = make_float4(0.f, 0.f, 0.f, 0.f);
            if (MODE == 1) {
                if (gm < N)
                    v = *reinterpret_cast<const float4*>(x + (size_t)gm * 128 + kc + q * 4);
            } else {
                if (gm < N) {
                    if (kc < 64) {
                        v = *reinterpret_cast<const float4*>(g_s2 + (size_t)gm * 64 + kc + q * 4);
                        float r = 1.0f / fmaxf((float)g_cnt[gm], 1.0f);
                        v.x *= r; v.y *= r; v.z *= r; v.w *= r;
                    } else {
                        size_t idx = (size_t)gm * 32 + ((kc - 64) >> 1) + q * 2;
                        float2 f0 = __half22float2(g_hh[idx]);
                        float2 f1 = __half22float2(g_hh[idx + 1]);
                        v = make_float4(f0.x, f0.y, f1.x, f1.y);
                    }
                }
            }
            va[it] = v;
        }
    };
    auto loadB = [&](int kc) {
#pragma unroll
        for (int it = 0; it < 4; it++) {
            int f = tid + it * 256;
            int n = f >> 3, q = f & 7;
            const float* src;
            if (MODE == 1)
                src = (n < 64) ? (Wl + (size_t)n * 128 + kc + q * 4)
                               : (Wr + (size_t)(n - 64) * 128 + kc + q * 4);
            else
                src = ((kc < 64) ? (Wl + (size_t)n * 64 + kc)
                                 : (Wr + (size_t)n * 64 + (kc - 64))) + q * 4;
            vb[it] = *reinterpret_cast<const float4*>(src);
        }
    };

    float acc[2][8][4];
#pragma unroll
    for (int i = 0; i < 2; i++)
#pragma unroll
        for (int j = 0; j < 8; j++)
#pragma unroll
            for (int q = 0; q < 4; q++) acc[i][j][q] = 0.f;

    loadA(0); loadB(0);

#pragma unroll
    for (int kc = 0; kc < 128; kc += 32) {
#pragma unroll
        for (int it = 0; it < 4; it++) {
            int f = tid + it * 256;
            int row = f >> 3, q = f & 7;
            int kl = q * 4;
            uint32_t* dstA = As + row * LDC;
            dstA[koff(kl + 0)] = f2tf32(va[it].x);
            dstA[koff(kl + 1)] = f2tf32(va[it].y);
            dstA[koff(kl + 2)] = f2tf32(va[it].z);
            dstA[koff(kl + 3)] = f2tf32(va[it].w);
            uint32_t* dstB = Bs + row * LDC;
            dstB[koff(kl + 0)] = f2tf32(vb[it].x);
            dstB[koff(kl + 1)] = f2tf32(vb[it].y);
            dstB[koff(kl + 2)] = f2tf32(vb[it].z);
            dstB[koff(kl + 3)] = f2tf32(vb[it].w);
        }
        __syncthreads();
        if (kc < 96) { loadA(kc + 32); loadB(kc + 32); }
#pragma unroll
        for (int s = 0; s < 4; s++) {
            uint32_t a[2][4];
#pragma unroll
            for (int mt = 0; mt < 2; mt++) {
                int m = rm + mt * 16 + g;
                uint2 lo = *reinterpret_cast<const uint2*>(As + m * LDC + s * 8 + t * 2);
                uint2 hi = *reinterpret_cast<const uint2*>(As + (m + 8) * LDC + s * 8 + t * 2);
                a[mt][0] = lo.x; a[mt][1] = hi.x; a[mt][2] = lo.y; a[mt][3] = hi.y;
            }
#pragma unroll
            for (int nt = 0; nt < 8; nt++) {
                uint2 b = *reinterpret_cast<const uint2*>(Bs + (cn + nt * 8 + g) * LDC + s * 8 + t * 2);
                MMA4(acc[0][nt], a[0], b);
                MMA4(acc[1][nt], a[1], b);
            }
        }
        __syncthreads();
    }
#pragma unroll
    for (int mt = 0; mt < 2; mt++) {
#pragma unroll
        for (int nt = 0; nt < 8; nt++) {
            int row = m0 + rm + mt * 16 + g;
            int col = cn + nt * 8 + t * 2;
            if (MODE == 1) {
                int c64 = nt * 8 + t * 2;
                if (cn == 0) {
                    if (row < N)
                        g_p1h[(size_t)row * 32 + (c64 >> 1)] =
                            __floats2half2_rn(acc[mt][nt][0], acc[mt][nt][1]);
                    if (row + 8 < N)
                        g_p1h[(size_t)(row + 8) * 32 + (c64 >> 1)] =
                            __floats2half2_rn(acc[mt][nt][2], acc[mt][nt][3]);
                } else {
                    if (row < N)
                        *reinterpret_cast<float2*>(g_q1 + (size_t)row * 64 + c64) =
                            make_float2(acc[mt][nt][0], acc[mt][nt][1]);
                    if (row + 8 < N)
                        *reinterpret_cast<float2*>(g_q1 + (size_t)(row + 8) * 64 + c64) =
                            make_float2(acc[mt][nt][2], acc[mt][nt][3]);
                }
            } else {
                float2 bb = *reinterpret_cast<const float2*>(bias + col);
                if (row < N)
                    *reinterpret_cast<float2*>(outp + (size_t)row * 128 + col) =
                        make_float2(acc[mt][nt][0] + bb.x, acc[mt][nt][1] + bb.y);
                if (row + 8 < N)
                    *reinterpret_cast<float2*>(outp + (size_t)(row + 8) * 128 + col) =
                        make_float2(acc[mt][nt][2] + bb.x, acc[mt][nt][3] + bb.y);
            }
        }
    }
}

// ---------------------------------------------------------------------------
extern "C" void kernel_launch(void* const* d_in, const int* in_sizes, int n_in,
                              void* d_out, int out_size)
{
    const float* x   = (const float*)d_in[0];
    const int*   ei  = (const int*)  d_in[1];
    const float* Wl1 = (const float*)d_in[2];
    const float* Wr1 = (const float*)d_in[3];
    const float* b1  = (const float*)d_in[4];
    const float* Wl2 = (const float*)d_in[5];
    const float* Wr2 = (const float*)d_in[6];
    const float* b2  = (const float*)d_in[7];
    float* out = (float*)d_out;

    int N = in_sizes[0] / 128;
    int E = in_sizes[1] / 2;

    int egrid  = (E + 255) / 256;
    int ngrid  = (N + 255) / 256;
    int ggrid  = (N + 127) / 128;
    int agrid  = (N * 32 + 255) / 256;
    int nb1    = (N + 511) / 512;

    // Fork a side stream for the CSR build so it overlaps GEMM1.
    // Host resources (stream/events) are created during the capture call only;
    // no device memory is involved. Event edges are graph-capturable.
    cudaStream_t s1;
    cudaEvent_t eFork, eJoin;
    cudaStreamCreateWithFlags(&s1, cudaStreamNonBlocking);
    cudaEventCreateWithFlags(&eFork, cudaEventDisableTiming);
    cudaEventCreateWithFlags(&eJoin, cudaEventDisableTiming);

    cudaEventRecord(eFork, 0);
    cudaStreamWaitEvent(s1, eFork, 0);

    // side stream: CSR build
    zero_cnt_kernel<<<(N / 4 + 256) / 256, 256, 0, s1>>>(N);
    hist_kernel<<<egrid, 256, 0, s1>>>(ei, E);
    scan1_kernel<<<nb1, 512, 0, s1>>>(N);
    scan23_kernel<<<ngrid, 256, 0, s1>>>(N, nb1);
    fill_kernel<<<egrid, 256, 0, s1>>>(ei, E);
    cudaEventRecord(eJoin, s1);

    // main (legacy) stream: GEMM1 concurrently
    gemm_tc<1><<<ggrid, 256>>>(x, Wl1, Wr1, nullptr, nullptr, N);

    // join, then the serial tail
    cudaStreamWaitEvent(0, eJoin, 0);
    agg_kernel<1><<<agrid, 256>>>(b1, N);
    agg_kernel<2><<<agrid, 256>>>(nullptr, N);
    gemm_tc<2><<<ggrid, 256>>>(nullptr, Wl2, Wr2, b2, out, N);
}